// round 2
// baseline (speedup 1.0000x reference)
#include <cuda_runtime.h>

#define THREADS 256
#define WARPS (THREADS / 32)
#define BINS 256
#define NBLOCKS (148 * 8)

__global__ void histc_zero_kernel(float* __restrict__ out, int n) {
    int i = blockIdx.x * blockDim.x + threadIdx.x;
    if (i < n) out[i] = 0.0f;
}

__global__ void histc_dup_kernel(float* __restrict__ out) {
    // Duplicate histogram into second output slot: out[256:512] = out[0:256]
    out[BINS + threadIdx.x] = out[threadIdx.x];
}

__global__ __launch_bounds__(THREADS) void histc_kernel(
    const float4* __restrict__ x, float* __restrict__ out, int n4)
{
    __shared__ unsigned int h[WARPS][BINS];

    // Zero private histograms
    unsigned int* hflat = &h[0][0];
    for (int i = threadIdx.x; i < WARPS * BINS; i += THREADS)
        hflat[i] = 0u;
    __syncthreads();

    unsigned int* hw = h[threadIdx.x >> 5];

    const int stride = gridDim.x * blockDim.x;
    for (int i = blockIdx.x * blockDim.x + threadIdx.x; i < n4; i += stride) {
        float4 v = x[i];

        // torch.histc: bins over [-4,4], x==4 -> last bin, outside ignored.
        // idx = floor((x - LO) * BINS/(HI-LO)) = floor((x+4)*32), clamped to 255.
        {
            float f = v.x;
            if (f >= -4.0f && f <= 4.0f) {
                int b = __float2int_rd((f + 4.0f) * 32.0f);
                b = min(b, BINS - 1);
                atomicAdd(&hw[b], 1u);
            }
        }
        {
            float f = v.y;
            if (f >= -4.0f && f <= 4.0f) {
                int b = __float2int_rd((f + 4.0f) * 32.0f);
                b = min(b, BINS - 1);
                atomicAdd(&hw[b], 1u);
            }
        }
        {
            float f = v.z;
            if (f >= -4.0f && f <= 4.0f) {
                int b = __float2int_rd((f + 4.0f) * 32.0f);
                b = min(b, BINS - 1);
                atomicAdd(&hw[b], 1u);
            }
        }
        {
            float f = v.w;
            if (f >= -4.0f && f <= 4.0f) {
                int b = __float2int_rd((f + 4.0f) * 32.0f);
                b = min(b, BINS - 1);
                atomicAdd(&hw[b], 1u);
            }
        }
    }
    __syncthreads();

    // Reduce warp-private copies and emit one global atomic per bin per block.
    for (int b = threadIdx.x; b < BINS; b += THREADS) {
        unsigned int s = 0;
        #pragma unroll
        for (int w = 0; w < WARPS; w++)
            s += h[w][b];
        if (s)
            atomicAdd(&out[b], (float)s);
    }
}

extern "C" void kernel_launch(void* const* d_in, const int* in_sizes, int n_in,
                              void* d_out, int out_size)
{
    const float4* x = (const float4*)d_in[0];
    float* out = (float*)d_out;
    int n4 = in_sizes[0] / 4;

    histc_zero_kernel<<<(out_size + 255) / 256, 256>>>(out, out_size);
    histc_kernel<<<NBLOCKS, THREADS>>>(x, out, n4);
    if (out_size >= 2 * BINS)
        histc_dup_kernel<<<1, BINS>>>(out);
}

// round 3
// speedup vs baseline: 1.1188x; 1.1188x over previous
#include <cuda_runtime.h>

#define THREADS 256
#define WARPS (THREADS / 32)
#define SUBHISTS (WARPS * 2)   // per-warp even/odd lane split
#define BINS 256
#define NBLOCKS (148 * 8)

__global__ void histc_zero_kernel(float* __restrict__ out, int n) {
    int i = blockIdx.x * blockDim.x + threadIdx.x;
    if (i < n) out[i] = 0.0f;
}

__device__ __forceinline__ void bin_one(float f, unsigned int* hw) {
    // torch.histc: bins over [-4,4], x==4 -> last bin, outside ignored.
    // (f+4)*32 == fmaf(f,32,128) bit-exactly (x32 is an exact binade shift).
    if (fabsf(f) <= 4.0f) {
        int b = __float2int_rd(fmaf(f, 32.0f, 128.0f));
        b = min(b, BINS - 1);
        atomicAdd(&hw[b], 1u);
    }
}

__device__ __forceinline__ void bin4(float4 v, unsigned int* hw) {
    bin_one(v.x, hw);
    bin_one(v.y, hw);
    bin_one(v.z, hw);
    bin_one(v.w, hw);
}

__global__ __launch_bounds__(THREADS) void histc_kernel(
    const float4* __restrict__ x, float* __restrict__ out, int n4, int dup)
{
    __shared__ unsigned int h[SUBHISTS][BINS];

    // Zero private histograms (16 KB)
    unsigned int* hflat = &h[0][0];
    #pragma unroll
    for (int i = threadIdx.x; i < SUBHISTS * BINS; i += THREADS)
        hflat[i] = 0u;
    __syncthreads();

    // Sub-histogram: per-warp, split by lane parity to halve atomic conflicts.
    unsigned int* hw = h[((threadIdx.x >> 5) << 1) | (threadIdx.x & 1)];

    const int stride = gridDim.x * blockDim.x;
    int i = blockIdx.x * blockDim.x + threadIdx.x;

    // Unroll x2: issue both 16B loads before any binning for MLP.
    for (; i + stride < n4; i += 2 * stride) {
        float4 a = __ldcs(&x[i]);
        float4 b = __ldcs(&x[i + stride]);
        bin4(a, hw);
        bin4(b, hw);
    }
    if (i < n4) {
        float4 a = __ldcs(&x[i]);
        bin4(a, hw);
    }
    __syncthreads();

    // Reduce the 16 sub-histograms; one thread per bin. Emit to both output
    // copies (reference returns (h, h)) to avoid a separate dup kernel.
    int b = threadIdx.x;
    unsigned int s = 0;
    #pragma unroll
    for (int w = 0; w < SUBHISTS; w++)
        s += h[w][b];
    if (s) {
        float fs = (float)s;
        atomicAdd(&out[b], fs);
        if (dup)
            atomicAdd(&out[b + BINS], fs);
    }
}

extern "C" void kernel_launch(void* const* d_in, const int* in_sizes, int n_in,
                              void* d_out, int out_size)
{
    const float4* x = (const float4*)d_in[0];
    float* out = (float*)d_out;
    int n4 = in_sizes[0] / 4;
    int dup = (out_size >= 2 * BINS) ? 1 : 0;

    histc_zero_kernel<<<(out_size + 255) / 256, 256>>>(out, out_size);
    histc_kernel<<<NBLOCKS, THREADS>>>(x, out, n4, dup);
}